// round 2
// baseline (speedup 1.0000x reference)
#include <cuda_runtime.h>
#include <cuda_bf16.h>
#include <float.h>

// Problem constants
#define BATCH   2
#define SEQ     4096
#define DIM     384
#define HEADS   6
#define HD      64
#define QK_SCALE 0.125f   // 64^-0.5

// Scratch (allocation-free requirement -> __device__ globals)
__device__ float g_q[BATCH * HEADS * SEQ * HD];   // [b,h,n,d]
__device__ float g_k[BATCH * HEADS * SEQ * HD];
__device__ float g_v[BATCH * HEADS * SEQ * HD];
__device__ float g_ao[BATCH * SEQ * DIM];         // attention out, [b,n,h*64+d]

// ---------------------------------------------------------------------------
// Kernel 1: qkv = x @ w_qkv^T, scattered into q/k/v [B,H,N,HD]
// C[m,n] = sum_k x[m,k] * w[n,k].  M=8192, N=1152, K=384.
// Tiles: 64x64x32, 256 threads, 4x4 micro-tile per thread.
// ---------------------------------------------------------------------------
__global__ __launch_bounds__(256) void qkv_gemm_kernel(
    const float* __restrict__ x, const float* __restrict__ w)
{
    __shared__ float As[32][64];
    __shared__ float Bs[32][64];

    const int bx = blockIdx.x;          // n-tile, 18
    const int by = blockIdx.y;          // m-tile, 128
    const int tid = threadIdx.x;
    const int tx = tid & 15;
    const int ty = tid >> 4;
    const int m0 = by * 64, n0 = bx * 64;

    float acc[4][4] = {};

    for (int k0 = 0; k0 < DIM; k0 += 32) {
#pragma unroll
        for (int u = 0; u < 2; ++u) {
            int i = tid + u * 256;                 // float4 index (512 total)
            int row = i >> 3;
            int kc = (i & 7) << 2;
            float4 av = *(const float4*)&x[(size_t)(m0 + row) * DIM + k0 + kc];
            As[kc + 0][row] = av.x; As[kc + 1][row] = av.y;
            As[kc + 2][row] = av.z; As[kc + 3][row] = av.w;
            float4 bv = *(const float4*)&w[(size_t)(n0 + row) * DIM + k0 + kc];
            Bs[kc + 0][row] = bv.x; Bs[kc + 1][row] = bv.y;
            Bs[kc + 2][row] = bv.z; Bs[kc + 3][row] = bv.w;
        }
        __syncthreads();
#pragma unroll
        for (int k = 0; k < 32; ++k) {
            float4 a4 = *(const float4*)&As[k][ty * 4];
            float4 b4 = *(const float4*)&Bs[k][tx * 4];
            float av[4] = {a4.x, a4.y, a4.z, a4.w};
            float bv[4] = {b4.x, b4.y, b4.z, b4.w};
#pragma unroll
            for (int i = 0; i < 4; ++i)
#pragma unroll
                for (int j = 0; j < 4; ++j)
                    acc[i][j] += av[i] * bv[j];
        }
        __syncthreads();
    }

    // Epilogue: n0 is a multiple of 64 and hd==64, so (sel,h) constant/block.
    const int sel = bx / HEADS;     // 0=q,1=k,2=v
    const int h   = bx % HEADS;
    float* dst = (sel == 0) ? g_q : (sel == 1 ? g_k : g_v);
#pragma unroll
    for (int i = 0; i < 4; ++i) {
        int m = m0 + ty * 4 + i;
        int b = m >> 12;            // /4096
        int nn = m & 4095;
        float* rowp = dst + (((size_t)(b * HEADS + h) * SEQ) + nn) * HD;
#pragma unroll
        for (int j = 0; j < 4; ++j)
            rowp[tx * 4 + j] = acc[i][j];
    }
}

// ---------------------------------------------------------------------------
// Kernel 2: flash attention per (b,h, 64-row q tile).
// 256 threads: thread t -> q-row r = t/4, hd-slice d0 = (t%4)*16.
// Masked score = -FLT_MAX (matches reference uniform-softmax on dead rows).
// mask arrives as int32 (harness converts JAX bool -> int32).
// ---------------------------------------------------------------------------
__global__ __launch_bounds__(256, 2) void attn_kernel(
    const int* __restrict__ mask)
{
    __shared__ float Ks[64][68];
    __shared__ float Vs[64][68];
    __shared__ int mk[64];

    const int qt = blockIdx.x;               // 64 q-tiles
    const int bh = blockIdx.y;               // 12 (b,h)
    const int b = bh / HEADS;

    const float* qbase = g_q + (size_t)bh * SEQ * HD;
    const float* kbase = g_k + (size_t)bh * SEQ * HD;
    const float* vbase = g_v + (size_t)bh * SEQ * HD;

    const int tid = threadIdx.x;
    const int r  = tid >> 2;
    const int lx = tid & 3;
    const int d0 = lx * 16;
    const int qrow = qt * 64 + r;

    float qreg[64];
    {
        const float4* qp = (const float4*)(qbase + (size_t)qrow * HD);
#pragma unroll
        for (int i = 0; i < 16; ++i) {
            float4 t = qp[i];
            qreg[4 * i + 0] = t.x; qreg[4 * i + 1] = t.y;
            qreg[4 * i + 2] = t.z; qreg[4 * i + 3] = t.w;
        }
    }
    const bool mq = mask[b * SEQ + qrow] != 0;

    float m_i = -FLT_MAX;
    float l_i = 0.f;
    float o[16] = {};

    for (int kt = 0; kt < SEQ / 64; ++kt) {
        // Load K/V 64x64 tiles (4 float4 per thread each)
#pragma unroll
        for (int u = 0; u < 4; ++u) {
            int i = tid + u * 256;             // 1024 float4 per matrix
            int c  = i >> 4;
            int dd = (i & 15) << 2;
            *(float4*)&Ks[c][dd] = *(const float4*)&kbase[(size_t)(kt * 64 + c) * HD + dd];
            *(float4*)&Vs[c][dd] = *(const float4*)&vbase[(size_t)(kt * 64 + c) * HD + dd];
        }
        if (tid < 64) mk[tid] = mask[b * SEQ + kt * 64 + tid];
        __syncthreads();

        // S = q . k^T over this thread's 16 columns (c = 4j + lx)
        float s[16];
#pragma unroll
        for (int j = 0; j < 16; ++j) {
            int c = 4 * j + lx;
            float ax = 0.f, ay = 0.f, az = 0.f, aw = 0.f;
#pragma unroll
            for (int dq = 0; dq < 16; ++dq) {
                float4 kv = *(const float4*)&Ks[c][dq * 4];
                ax += qreg[dq * 4 + 0] * kv.x;
                ay += qreg[dq * 4 + 1] * kv.y;
                az += qreg[dq * 4 + 2] * kv.z;
                aw += qreg[dq * 4 + 3] * kv.w;
            }
            float sv = (ax + ay) + (az + aw);
            s[j] = (mq && (mk[c] != 0)) ? sv * QK_SCALE : -FLT_MAX;
        }

        // online softmax: group-of-4 reductions
        float tm = s[0];
#pragma unroll
        for (int j = 1; j < 16; ++j) tm = fmaxf(tm, s[j]);
        tm = fmaxf(tm, __shfl_xor_sync(0xffffffffu, tm, 1, 4));
        tm = fmaxf(tm, __shfl_xor_sync(0xffffffffu, tm, 2, 4));
        float m_new = fmaxf(m_i, tm);
        float alpha = __expf(m_i - m_new);

        float ps = 0.f;
#pragma unroll
        for (int j = 0; j < 16; ++j) {
            float p = __expf(s[j] - m_new);
            s[j] = p;
            ps += p;
        }
        ps += __shfl_xor_sync(0xffffffffu, ps, 1, 4);
        ps += __shfl_xor_sync(0xffffffffu, ps, 2, 4);
        l_i = l_i * alpha + ps;
        m_i = m_new;

#pragma unroll
        for (int j = 0; j < 16; ++j) o[j] *= alpha;

        // O += P @ V : share P across the 4-thread row group via shuffles
#pragma unroll
        for (int j = 0; j < 16; ++j) {
#pragma unroll
            for (int xx = 0; xx < 4; ++xx) {
                float pv = __shfl_sync(0xffffffffu, s[j], xx, 4);
                int c = 4 * j + xx;
#pragma unroll
                for (int u = 0; u < 4; ++u) {
                    float4 vv = *(const float4*)&Vs[c][d0 + u * 4];
                    o[u * 4 + 0] += pv * vv.x;
                    o[u * 4 + 1] += pv * vv.y;
                    o[u * 4 + 2] += pv * vv.z;
                    o[u * 4 + 3] += pv * vv.w;
                }
            }
        }
        __syncthreads();
    }

    const float inv = 1.f / l_i;
    const int h = bh % HEADS;
    float* outp = g_ao + ((size_t)b * SEQ + qrow) * DIM + h * HD + d0;
#pragma unroll
    for (int j = 0; j < 16; ++j) outp[j] = o[j] * inv;
}

// ---------------------------------------------------------------------------
// Kernel 3: out = g_ao @ w_proj^T + b_proj.  M=8192, N=384, K=384.
// ---------------------------------------------------------------------------
__global__ __launch_bounds__(256) void proj_gemm_kernel(
    const float* __restrict__ w, const float* __restrict__ bias,
    float* __restrict__ out)
{
    __shared__ float As[32][64];
    __shared__ float Bs[32][64];

    const int bx = blockIdx.x;          // n-tile, 6
    const int by = blockIdx.y;          // m-tile, 128
    const int tid = threadIdx.x;
    const int tx = tid & 15;
    const int ty = tid >> 4;
    const int m0 = by * 64, n0 = bx * 64;

    float acc[4][4] = {};

    for (int k0 = 0; k0 < DIM; k0 += 32) {
#pragma unroll
        for (int u = 0; u < 2; ++u) {
            int i = tid + u * 256;
            int row = i >> 3;
            int kc = (i & 7) << 2;
            float4 av = *(const float4*)&g_ao[(size_t)(m0 + row) * DIM + k0 + kc];
            As[kc + 0][row] = av.x; As[kc + 1][row] = av.y;
            As[kc + 2][row] = av.z; As[kc + 3][row] = av.w;
            float4 bv = *(const float4*)&w[(size_t)(n0 + row) * DIM + k0 + kc];
            Bs[kc + 0][row] = bv.x; Bs[kc + 1][row] = bv.y;
            Bs[kc + 2][row] = bv.z; Bs[kc + 3][row] = bv.w;
        }
        __syncthreads();
#pragma unroll
        for (int k = 0; k < 32; ++k) {
            float4 a4 = *(const float4*)&As[k][ty * 4];
            float4 b4 = *(const float4*)&Bs[k][tx * 4];
            float av[4] = {a4.x, a4.y, a4.z, a4.w};
            float bv[4] = {b4.x, b4.y, b4.z, b4.w};
#pragma unroll
            for (int i = 0; i < 4; ++i)
#pragma unroll
                for (int j = 0; j < 4; ++j)
                    acc[i][j] += av[i] * bv[j];
        }
        __syncthreads();
    }

#pragma unroll
    for (int i = 0; i < 4; ++i) {
        int m = m0 + ty * 4 + i;
#pragma unroll
        for (int j = 0; j < 4; ++j) {
            int n = n0 + tx * 4 + j;
            out[(size_t)m * DIM + n] = acc[i][j] + bias[n];
        }
    }
}

// ---------------------------------------------------------------------------
extern "C" void kernel_launch(void* const* d_in, const int* in_sizes, int n_in,
                              void* d_out, int out_size)
{
    const float* x      = (const float*)d_in[0];
    const int*   mask   = (const int*)d_in[1];     // JAX bool -> int32
    const float* w_qkv  = (const float*)d_in[2];
    const float* w_proj = (const float*)d_in[3];
    const float* b_proj = (const float*)d_in[4];
    float*       out    = (float*)d_out;

    dim3 g1(3 * DIM / 64, (BATCH * SEQ) / 64);   // (18, 128)
    qkv_gemm_kernel<<<g1, 256>>>(x, w_qkv);

    dim3 g2(SEQ / 64, BATCH * HEADS);            // (64, 12)
    attn_kernel<<<g2, 256>>>(mask);

    dim3 g3(DIM / 64, (BATCH * SEQ) / 64);       // (6, 128)
    proj_gemm_kernel<<<g3, 256>>>(w_proj, b_proj, out);
}

// round 3
// speedup vs baseline: 5.8218x; 5.8218x over previous
#include <cuda_runtime.h>
#include <cuda_bf16.h>
#include <float.h>

// Problem constants
#define BATCH   2
#define SEQ     4096
#define DIM     384
#define HEADS   6
#define HD      64
#define QK_SCALE 0.125f   // 64^-0.5

// Scratch (allocation-free requirement -> __device__ globals)
__device__ float g_q[BATCH * HEADS * SEQ * HD];   // [b,h,n,d]
__device__ float g_k[BATCH * HEADS * SEQ * HD];
__device__ float g_v[BATCH * HEADS * SEQ * HD];
__device__ float g_ao[BATCH * SEQ * DIM];         // attention out, [b,n,h*64+d]

// ---------------------------------------------------------------------------
// helpers: tf32 convert + m16n8k8 tf32 mma
// ---------------------------------------------------------------------------
__device__ __forceinline__ unsigned tf32_of(float f) {
    unsigned u;
    asm("cvt.rna.tf32.f32 %0, %1;" : "=r"(u) : "f"(f));
    return u;
}

__device__ __forceinline__ void mma_tf32(float* c, const unsigned* a, const unsigned* b) {
    asm volatile(
        "mma.sync.aligned.m16n8k8.row.col.f32.tf32.tf32.f32 "
        "{%0,%1,%2,%3}, {%4,%5,%6,%7}, {%8,%9}, {%0,%1,%2,%3};"
        : "+f"(c[0]), "+f"(c[1]), "+f"(c[2]), "+f"(c[3])
        : "r"(a[0]), "r"(a[1]), "r"(a[2]), "r"(a[3]), "r"(b[0]), "r"(b[1]));
}

// ---------------------------------------------------------------------------
// Kernel 1: qkv = x @ w_qkv^T, scattered into q/k/v [B,H,N,HD]  (fp32)
// ---------------------------------------------------------------------------
__global__ __launch_bounds__(256) void qkv_gemm_kernel(
    const float* __restrict__ x, const float* __restrict__ w)
{
    __shared__ float As[32][64];
    __shared__ float Bs[32][64];

    const int bx = blockIdx.x;          // n-tile, 18
    const int by = blockIdx.y;          // m-tile, 128
    const int tid = threadIdx.x;
    const int tx = tid & 15;
    const int ty = tid >> 4;
    const int m0 = by * 64, n0 = bx * 64;

    float acc[4][4] = {};

    for (int k0 = 0; k0 < DIM; k0 += 32) {
#pragma unroll
        for (int u = 0; u < 2; ++u) {
            int i = tid + u * 256;                 // float4 index (512 total)
            int row = i >> 3;
            int kc = (i & 7) << 2;
            float4 av = *(const float4*)&x[(size_t)(m0 + row) * DIM + k0 + kc];
            As[kc + 0][row] = av.x; As[kc + 1][row] = av.y;
            As[kc + 2][row] = av.z; As[kc + 3][row] = av.w;
            float4 bv = *(const float4*)&w[(size_t)(n0 + row) * DIM + k0 + kc];
            Bs[kc + 0][row] = bv.x; Bs[kc + 1][row] = bv.y;
            Bs[kc + 2][row] = bv.z; Bs[kc + 3][row] = bv.w;
        }
        __syncthreads();
#pragma unroll
        for (int k = 0; k < 32; ++k) {
            float4 a4 = *(const float4*)&As[k][ty * 4];
            float4 b4 = *(const float4*)&Bs[k][tx * 4];
            float av[4] = {a4.x, a4.y, a4.z, a4.w};
            float bv[4] = {b4.x, b4.y, b4.z, b4.w};
#pragma unroll
            for (int i = 0; i < 4; ++i)
#pragma unroll
                for (int j = 0; j < 4; ++j)
                    acc[i][j] += av[i] * bv[j];
        }
        __syncthreads();
    }

    const int sel = bx / HEADS;     // 0=q,1=k,2=v
    const int h   = bx % HEADS;
    float* dst = (sel == 0) ? g_q : (sel == 1 ? g_k : g_v);
#pragma unroll
    for (int i = 0; i < 4; ++i) {
        int m = m0 + ty * 4 + i;
        int b = m >> 12;            // /4096
        int nn = m & 4095;
        float* rowp = dst + (((size_t)(b * HEADS + h) * SEQ) + nn) * HD;
#pragma unroll
        for (int j = 0; j < 4; ++j)
            rowp[tx * 4 + j] = acc[i][j];
    }
}

// ---------------------------------------------------------------------------
// Kernel 2: flash attention on tensor cores (tf32 mma).
// CTA: 256 threads (8 warps), q-tile 128 rows (16/warp), kv-tile 64.
// ---------------------------------------------------------------------------
__global__ __launch_bounds__(256, 2) void attn_kernel(
    const int* __restrict__ mask)
{
    __shared__ float Ks[64][68];   // stride 68: conflict-free for K B-frag quads
    __shared__ float Vs[64][72];   // stride 72: conflict-free for V B-frag quads
    __shared__ int mk[64];

    const int qt = blockIdx.x;               // 32 q-tiles of 128 rows
    const int bh = blockIdx.y;               // 12 (b,h)
    const int b = bh / HEADS, h = bh % HEADS;
    const int tid = threadIdx.x;
    const int w  = tid >> 5;
    const int l  = tid & 31;
    const int lq = l >> 2;                   // 0..7
    const int lr = l & 3;                    // 0..3

    const float* qbase = g_q + (size_t)bh * SEQ * HD;
    const float* kbase = g_k + (size_t)bh * SEQ * HD;
    const float* vbase = g_v + (size_t)bh * SEQ * HD;

    const int q0 = qt * 128 + w * 16;
    const int r0 = q0 + lq;                  // this thread's first c-frag row

    // Q as tf32 A-fragments over 8 k-tiles of hd, scale folded in
    unsigned aQ[8][4];
#pragma unroll
    for (int kk = 0; kk < 8; ++kk) {
        aQ[kk][0] = tf32_of(qbase[(size_t)r0 * HD + kk * 8 + lr] * QK_SCALE);
        aQ[kk][1] = tf32_of(qbase[(size_t)(r0 + 8) * HD + kk * 8 + lr] * QK_SCALE);
        aQ[kk][2] = tf32_of(qbase[(size_t)r0 * HD + kk * 8 + lr + 4] * QK_SCALE);
        aQ[kk][3] = tf32_of(qbase[(size_t)(r0 + 8) * HD + kk * 8 + lr + 4] * QK_SCALE);
    }
    const bool mq0 = mask[b * SEQ + r0] != 0;
    const bool mq1 = mask[b * SEQ + r0 + 8] != 0;

    float O[8][4] = {};
    float m0 = -FLT_MAX, m1 = -FLT_MAX;
    float l0 = 0.f, l1 = 0.f;

    for (int kt = 0; kt < SEQ / 64; ++kt) {
        __syncthreads();
        // load K/V 64x64 tiles, rounding to tf32 at store
#pragma unroll
        for (int u = 0; u < 4; ++u) {
            int i = tid + u * 256;             // 1024 float4 per matrix
            int c  = i >> 4;
            int dd = (i & 15) << 2;
            float4 kv = *(const float4*)&kbase[(size_t)(kt * 64 + c) * HD + dd];
            Ks[c][dd + 0] = __uint_as_float(tf32_of(kv.x));
            Ks[c][dd + 1] = __uint_as_float(tf32_of(kv.y));
            Ks[c][dd + 2] = __uint_as_float(tf32_of(kv.z));
            Ks[c][dd + 3] = __uint_as_float(tf32_of(kv.w));
            float4 vv = *(const float4*)&vbase[(size_t)(kt * 64 + c) * HD + dd];
            Vs[c][dd + 0] = __uint_as_float(tf32_of(vv.x));
            Vs[c][dd + 1] = __uint_as_float(tf32_of(vv.y));
            Vs[c][dd + 2] = __uint_as_float(tf32_of(vv.z));
            Vs[c][dd + 3] = __uint_as_float(tf32_of(vv.w));
        }
        if (tid < 64) mk[tid] = mask[b * SEQ + kt * 64 + tid];
        __syncthreads();

        // ----- S = (Q*scale) @ K^T : 8 n-tiles x 8 k-tiles of mma -----
        float sc[8][4];
#pragma unroll
        for (int nt = 0; nt < 8; ++nt) { sc[nt][0] = sc[nt][1] = sc[nt][2] = sc[nt][3] = 0.f; }
#pragma unroll
        for (int nt = 0; nt < 8; ++nt) {
#pragma unroll
            for (int kk = 0; kk < 8; ++kk) {
                unsigned bk[2];
                bk[0] = __float_as_uint(Ks[nt * 8 + lq][kk * 8 + lr]);
                bk[1] = __float_as_uint(Ks[nt * 8 + lq][kk * 8 + lr + 4]);
                mma_tf32(sc[nt], aQ[kk], bk);
            }
        }

        // ----- mask + row max -----
        float t0 = -FLT_MAX, t1 = -FLT_MAX;
#pragma unroll
        for (int nt = 0; nt < 8; ++nt) {
            int c0 = nt * 8 + lr * 2;
            bool mc0 = mk[c0] != 0;
            bool mc1 = mk[c0 + 1] != 0;
            if (!(mq0 && mc0)) sc[nt][0] = -FLT_MAX;
            if (!(mq0 && mc1)) sc[nt][1] = -FLT_MAX;
            if (!(mq1 && mc0)) sc[nt][2] = -FLT_MAX;
            if (!(mq1 && mc1)) sc[nt][3] = -FLT_MAX;
            t0 = fmaxf(t0, fmaxf(sc[nt][0], sc[nt][1]));
            t1 = fmaxf(t1, fmaxf(sc[nt][2], sc[nt][3]));
        }
        t0 = fmaxf(t0, __shfl_xor_sync(0xffffffffu, t0, 1));
        t0 = fmaxf(t0, __shfl_xor_sync(0xffffffffu, t0, 2));
        t1 = fmaxf(t1, __shfl_xor_sync(0xffffffffu, t1, 1));
        t1 = fmaxf(t1, __shfl_xor_sync(0xffffffffu, t1, 2));

        float mn0 = fmaxf(m0, t0), mn1 = fmaxf(m1, t1);
        float al0 = __expf(m0 - mn0), al1 = __expf(m1 - mn1);
        m0 = mn0; m1 = mn1;

        float ps0 = 0.f, ps1 = 0.f;
#pragma unroll
        for (int nt = 0; nt < 8; ++nt) {
            sc[nt][0] = __expf(sc[nt][0] - mn0);
            sc[nt][1] = __expf(sc[nt][1] - mn0);
            sc[nt][2] = __expf(sc[nt][2] - mn1);
            sc[nt][3] = __expf(sc[nt][3] - mn1);
            ps0 += sc[nt][0] + sc[nt][1];
            ps1 += sc[nt][2] + sc[nt][3];
        }
        ps0 += __shfl_xor_sync(0xffffffffu, ps0, 1);
        ps0 += __shfl_xor_sync(0xffffffffu, ps0, 2);
        ps1 += __shfl_xor_sync(0xffffffffu, ps1, 1);
        ps1 += __shfl_xor_sync(0xffffffffu, ps1, 2);
        l0 = l0 * al0 + ps0;
        l1 = l1 * al1 + ps1;

#pragma unroll
        for (int nt = 0; nt < 8; ++nt) {
            O[nt][0] *= al0; O[nt][1] *= al0;
            O[nt][2] *= al1; O[nt][3] *= al1;
        }

        // ----- O += P @ V -----
        const int srcA = (l & ~3) + (lr >> 1);
        const bool par = (lr & 1) != 0;
#pragma unroll
        for (int kk = 0; kk < 8; ++kk) {
            // C-frag (cols 2c,2c+1) -> A-frag (cols c,c+4) via intra-quad shuffles
            float x0 = __shfl_sync(0xffffffffu, sc[kk][0], srcA);
            float x1 = __shfl_sync(0xffffffffu, sc[kk][1], srcA);
            float x2 = __shfl_sync(0xffffffffu, sc[kk][2], srcA);
            float x3 = __shfl_sync(0xffffffffu, sc[kk][3], srcA);
            float y0 = __shfl_sync(0xffffffffu, sc[kk][0], srcA + 2);
            float y1 = __shfl_sync(0xffffffffu, sc[kk][1], srcA + 2);
            float y2 = __shfl_sync(0xffffffffu, sc[kk][2], srcA + 2);
            float y3 = __shfl_sync(0xffffffffu, sc[kk][3], srcA + 2);
            unsigned aP[4];
            aP[0] = tf32_of(par ? x1 : x0);
            aP[1] = tf32_of(par ? x3 : x2);
            aP[2] = tf32_of(par ? y1 : y0);
            aP[3] = tf32_of(par ? y3 : y2);
#pragma unroll
            for (int nt = 0; nt < 8; ++nt) {
                unsigned bv[2];
                bv[0] = __float_as_uint(Vs[kk * 8 + lr][nt * 8 + lq]);
                bv[1] = __float_as_uint(Vs[kk * 8 + lr + 4][nt * 8 + lq]);
                mma_tf32(O[nt], aP, bv);
            }
        }
    }

    // epilogue
    const float inv0 = 1.f / l0;
    const float inv1 = 1.f / l1;
    float* orow0 = g_ao + ((size_t)b * SEQ + r0) * DIM + h * HD;
    float* orow1 = orow0 + 8 * DIM;
#pragma unroll
    for (int nt = 0; nt < 8; ++nt) {
        int c = nt * 8 + lr * 2;
        float2 v0 = make_float2(O[nt][0] * inv0, O[nt][1] * inv0);
        float2 v1 = make_float2(O[nt][2] * inv1, O[nt][3] * inv1);
        *(float2*)&orow0[c] = v0;
        *(float2*)&orow1[c] = v1;
    }
}

// ---------------------------------------------------------------------------
// Kernel 3: out = g_ao @ w_proj^T + b_proj.  (fp32)
// ---------------------------------------------------------------------------
__global__ __launch_bounds__(256) void proj_gemm_kernel(
    const float* __restrict__ w, const float* __restrict__ bias,
    float* __restrict__ out)
{
    __shared__ float As[32][64];
    __shared__ float Bs[32][64];

    const int bx = blockIdx.x;          // n-tile, 6
    const int by = blockIdx.y;          // m-tile, 128
    const int tid = threadIdx.x;
    const int tx = tid & 15;
    const int ty = tid >> 4;
    const int m0 = by * 64, n0 = bx * 64;

    float acc[4][4] = {};

    for (int k0 = 0; k0 < DIM; k0 += 32) {
#pragma unroll
        for (int u = 0; u < 2; ++u) {
            int i = tid + u * 256;
            int row = i >> 3;
            int kc = (i & 7) << 2;
            float4 av = *(const float4*)&g_ao[(size_t)(m0 + row) * DIM + k0 + kc];
            As[kc + 0][row] = av.x; As[kc + 1][row] = av.y;
            As[kc + 2][row] = av.z; As[kc + 3][row] = av.w;
            float4 bv = *(const float4*)&w[(size_t)(n0 + row) * DIM + k0 + kc];
            Bs[kc + 0][row] = bv.x; Bs[kc + 1][row] = bv.y;
            Bs[kc + 2][row] = bv.z; Bs[kc + 3][row] = bv.w;
        }
        __syncthreads();
#pragma unroll
        for (int k = 0; k < 32; ++k) {
            float4 a4 = *(const float4*)&As[k][ty * 4];
            float4 b4 = *(const float4*)&Bs[k][tx * 4];
            float av[4] = {a4.x, a4.y, a4.z, a4.w};
            float bv[4] = {b4.x, b4.y, b4.z, b4.w};
#pragma unroll
            for (int i = 0; i < 4; ++i)
#pragma unroll
                for (int j = 0; j < 4; ++j)
                    acc[i][j] += av[i] * bv[j];
        }
        __syncthreads();
    }

#pragma unroll
    for (int i = 0; i < 4; ++i) {
        int m = m0 + ty * 4 + i;
#pragma unroll
        for (int j = 0; j < 4; ++j) {
            int n = n0 + tx * 4 + j;
            out[(size_t)m * DIM + n] = acc[i][j] + bias[n];
        }
    }
}

// ---------------------------------------------------------------------------
extern "C" void kernel_launch(void* const* d_in, const int* in_sizes, int n_in,
                              void* d_out, int out_size)
{
    const float* x      = (const float*)d_in[0];
    const int*   mask   = (const int*)d_in[1];     // JAX bool -> int32
    const float* w_qkv  = (const float*)d_in[2];
    const float* w_proj = (const float*)d_in[3];
    const float* b_proj = (const float*)d_in[4];
    float*       out    = (float*)d_out;

    dim3 g1(3 * DIM / 64, (BATCH * SEQ) / 64);   // (18, 128)
    qkv_gemm_kernel<<<g1, 256>>>(x, w_qkv);

    dim3 g2(SEQ / 128, BATCH * HEADS);           // (32, 12)
    attn_kernel<<<g2, 256>>>(mask);

    dim3 g3(DIM / 64, (BATCH * SEQ) / 64);       // (6, 128)
    proj_gemm_kernel<<<g3, 256>>>(w_proj, b_proj, out);
}

// round 5
// speedup vs baseline: 7.4211x; 1.2747x over previous
#include <cuda_runtime.h>
#include <cuda_bf16.h>
#include <float.h>

// Problem constants
#define BATCH   2
#define SEQ     4096
#define DIM     384
#define HEADS   6
#define HD      64
#define QK_SCALE 0.125f   // 64^-0.5

// Scratch (allocation-free requirement -> __device__ globals)
__device__ float g_q[BATCH * HEADS * SEQ * HD];   // [b,h,n,d]
__device__ float g_k[BATCH * HEADS * SEQ * HD];
__device__ float g_v[BATCH * HEADS * SEQ * HD];
__device__ float g_ao[BATCH * SEQ * DIM];         // attention out, [b,n,h*64+d]

// ---------------------------------------------------------------------------
// helpers
// ---------------------------------------------------------------------------
__device__ __forceinline__ unsigned tf32_of(float f) {
    unsigned u;
    asm("cvt.rna.tf32.f32 %0, %1;" : "=r"(u) : "f"(f));
    return u;
}

__device__ __forceinline__ void mma_tf32(float* c, const unsigned* a, const unsigned* b) {
    asm volatile(
        "mma.sync.aligned.m16n8k8.row.col.f32.tf32.tf32.f32 "
        "{%0,%1,%2,%3}, {%4,%5,%6,%7}, {%8,%9}, {%0,%1,%2,%3};"
        : "+f"(c[0]), "+f"(c[1]), "+f"(c[2]), "+f"(c[3])
        : "r"(a[0]), "r"(a[1]), "r"(a[2]), "r"(a[3]), "r"(b[0]), "r"(b[1]));
}

#define CP16(dst, src) \
    asm volatile("cp.async.cg.shared.global [%0], [%1], 16;" :: \
        "r"((unsigned)__cvta_generic_to_shared(dst)), "l"(src))

// ---------------------------------------------------------------------------
// Kernel 1: qkv = x @ w_qkv^T on tensor cores (tf32 x3 compensation).
// M=8192, N=1152, K=384.  CTA tile 128x64, 8 warps (4m x 2n), warp 32x32.
// K chunked by 16, cp.async double-buffered.
// ---------------------------------------------------------------------------
__global__ __launch_bounds__(256, 2) void qkv_gemm_tc(
    const float* __restrict__ x, const float* __restrict__ w)
{
    __shared__ __align__(16) float As[2][128][20];
    __shared__ __align__(16) float Bs[2][64][20];

    const int bx = blockIdx.x;          // n-tile, 18
    const int by = blockIdx.y;          // m-tile, 64
    const int tid = threadIdx.x;
    const int wid = tid >> 5;
    const int l   = tid & 31;
    const int lq  = l >> 2;
    const int lr  = l & 3;
    const int wm  = (wid >> 1) * 32;
    const int wn  = (wid & 1) * 32;
    const int m0 = by * 128, n0 = bx * 64;

    const int lrow = tid >> 2;           // 0..63
    const int lkc  = (tid & 3) << 2;     // 0,4,8,12

    float C[2][4][4] = {};

    // prologue: stage 0
    CP16(&As[0][lrow][lkc],      &x[(size_t)(m0 + lrow) * DIM + lkc]);
    CP16(&As[0][lrow + 64][lkc], &x[(size_t)(m0 + lrow + 64) * DIM + lkc]);
    CP16(&Bs[0][lrow][lkc],      &w[(size_t)(n0 + lrow) * DIM + lkc]);
    asm volatile("cp.async.commit_group;" ::: "memory");

    const int NITER = DIM / 16;          // 24
    for (int it = 0; it < NITER; ++it) {
        if (it + 1 < NITER) {
            int k0 = (it + 1) * 16;
            int nb = (it + 1) & 1;
            CP16(&As[nb][lrow][lkc],      &x[(size_t)(m0 + lrow) * DIM + k0 + lkc]);
            CP16(&As[nb][lrow + 64][lkc], &x[(size_t)(m0 + lrow + 64) * DIM + k0 + lkc]);
            CP16(&Bs[nb][lrow][lkc],      &w[(size_t)(n0 + lrow) * DIM + k0 + lkc]);
            asm volatile("cp.async.commit_group;" ::: "memory");
            asm volatile("cp.async.wait_group 1;" ::: "memory");
        } else {
            asm volatile("cp.async.wait_group 0;" ::: "memory");
        }
        __syncthreads();
        const int buf = it & 1;

#pragma unroll
        for (int ks = 0; ks < 2; ++ks) {
            const int kb = ks * 8;
            unsigned ah[2][4], al[2][4];
#pragma unroll
            for (int mt = 0; mt < 2; ++mt) {
                float a0 = As[buf][wm + mt * 16 + lq][kb + lr];
                float a1 = As[buf][wm + mt * 16 + lq + 8][kb + lr];
                float a2 = As[buf][wm + mt * 16 + lq][kb + lr + 4];
                float a3 = As[buf][wm + mt * 16 + lq + 8][kb + lr + 4];
                ah[mt][0] = tf32_of(a0); al[mt][0] = tf32_of(a0 - __uint_as_float(ah[mt][0]));
                ah[mt][1] = tf32_of(a1); al[mt][1] = tf32_of(a1 - __uint_as_float(ah[mt][1]));
                ah[mt][2] = tf32_of(a2); al[mt][2] = tf32_of(a2 - __uint_as_float(ah[mt][2]));
                ah[mt][3] = tf32_of(a3); al[mt][3] = tf32_of(a3 - __uint_as_float(ah[mt][3]));
            }
            unsigned bh[4][2], bl[4][2];
#pragma unroll
            for (int nt = 0; nt < 4; ++nt) {
                float b0 = Bs[buf][wn + nt * 8 + lq][kb + lr];
                float b1 = Bs[buf][wn + nt * 8 + lq][kb + lr + 4];
                bh[nt][0] = tf32_of(b0); bl[nt][0] = tf32_of(b0 - __uint_as_float(bh[nt][0]));
                bh[nt][1] = tf32_of(b1); bl[nt][1] = tf32_of(b1 - __uint_as_float(bh[nt][1]));
            }
#pragma unroll
            for (int mt = 0; mt < 2; ++mt)
#pragma unroll
                for (int nt = 0; nt < 4; ++nt) {
                    mma_tf32(C[mt][nt], al[mt], bh[nt]);
                    mma_tf32(C[mt][nt], ah[mt], bl[nt]);
                    mma_tf32(C[mt][nt], ah[mt], bh[nt]);
                }
        }
        __syncthreads();
    }

    // epilogue: scatter to q/k/v [b,h,n,d]
    const int sel = bx / HEADS;     // 0=q,1=k,2=v
    const int h   = bx % HEADS;
    float* dst = (sel == 0) ? g_q : (sel == 1 ? g_k : g_v);
#pragma unroll
    for (int mt = 0; mt < 2; ++mt) {
        int m = m0 + wm + mt * 16 + lq;
        int b = m >> 12;
        int nn = m & 4095;
        float* p = dst + ((size_t)(b * HEADS + h) * SEQ + nn) * HD;
#pragma unroll
        for (int nt = 0; nt < 4; ++nt) {
            int n = wn + nt * 8 + lr * 2;
            *(float2*)&p[n]            = make_float2(C[mt][nt][0], C[mt][nt][1]);
            *(float2*)&p[8 * HD + n]   = make_float2(C[mt][nt][2], C[mt][nt][3]);
        }
    }
}

// ---------------------------------------------------------------------------
// Kernel 2: flash attention on tensor cores (tf32 mma).  (unchanged)
// ---------------------------------------------------------------------------
__global__ __launch_bounds__(256, 2) void attn_kernel(
    const int* __restrict__ mask)
{
    __shared__ float Ks[64][68];
    __shared__ float Vs[64][72];
    __shared__ int mk[64];

    const int qt = blockIdx.x;               // 32 q-tiles of 128 rows
    const int bh = blockIdx.y;               // 12 (b,h)
    const int b = bh / HEADS, h = bh % HEADS;
    const int tid = threadIdx.x;
    const int w  = tid >> 5;
    const int l  = tid & 31;
    const int lq = l >> 2;
    const int lr = l & 3;

    const float* qbase = g_q + (size_t)bh * SEQ * HD;
    const float* kbase = g_k + (size_t)bh * SEQ * HD;
    const float* vbase = g_v + (size_t)bh * SEQ * HD;

    const int q0 = qt * 128 + w * 16;
    const int r0 = q0 + lq;

    unsigned aQ[8][4];
#pragma unroll
    for (int kk = 0; kk < 8; ++kk) {
        aQ[kk][0] = tf32_of(qbase[(size_t)r0 * HD + kk * 8 + lr] * QK_SCALE);
        aQ[kk][1] = tf32_of(qbase[(size_t)(r0 + 8) * HD + kk * 8 + lr] * QK_SCALE);
        aQ[kk][2] = tf32_of(qbase[(size_t)r0 * HD + kk * 8 + lr + 4] * QK_SCALE);
        aQ[kk][3] = tf32_of(qbase[(size_t)(r0 + 8) * HD + kk * 8 + lr + 4] * QK_SCALE);
    }
    const bool mq0 = mask[b * SEQ + r0] != 0;
    const bool mq1 = mask[b * SEQ + r0 + 8] != 0;

    float O[8][4] = {};
    float m0 = -FLT_MAX, m1 = -FLT_MAX;
    float l0 = 0.f, l1 = 0.f;

    for (int kt = 0; kt < SEQ / 64; ++kt) {
        __syncthreads();
#pragma unroll
        for (int u = 0; u < 4; ++u) {
            int i = tid + u * 256;
            int c  = i >> 4;
            int dd = (i & 15) << 2;
            float4 kv = *(const float4*)&kbase[(size_t)(kt * 64 + c) * HD + dd];
            Ks[c][dd + 0] = __uint_as_float(tf32_of(kv.x));
            Ks[c][dd + 1] = __uint_as_float(tf32_of(kv.y));
            Ks[c][dd + 2] = __uint_as_float(tf32_of(kv.z));
            Ks[c][dd + 3] = __uint_as_float(tf32_of(kv.w));
            float4 vv = *(const float4*)&vbase[(size_t)(kt * 64 + c) * HD + dd];
            Vs[c][dd + 0] = __uint_as_float(tf32_of(vv.x));
            Vs[c][dd + 1] = __uint_as_float(tf32_of(vv.y));
            Vs[c][dd + 2] = __uint_as_float(tf32_of(vv.z));
            Vs[c][dd + 3] = __uint_as_float(tf32_of(vv.w));
        }
        if (tid < 64) mk[tid] = mask[b * SEQ + kt * 64 + tid];
        __syncthreads();

        float sc[8][4];
#pragma unroll
        for (int nt = 0; nt < 8; ++nt) { sc[nt][0] = sc[nt][1] = sc[nt][2] = sc[nt][3] = 0.f; }
#pragma unroll
        for (int nt = 0; nt < 8; ++nt) {
#pragma unroll
            for (int kk = 0; kk < 8; ++kk) {
                unsigned bk[2];
                bk[0] = __float_as_uint(Ks[nt * 8 + lq][kk * 8 + lr]);
                bk[1] = __float_as_uint(Ks[nt * 8 + lq][kk * 8 + lr + 4]);
                mma_tf32(sc[nt], aQ[kk], bk);
            }
        }

        float t0 = -FLT_MAX, t1 = -FLT_MAX;
#pragma unroll
        for (int nt = 0; nt < 8; ++nt) {
            int c0 = nt * 8 + lr * 2;
            bool mc0 = mk[c0] != 0;
            bool mc1 = mk[c0 + 1] != 0;
            if (!(mq0 && mc0)) sc[nt][0] = -FLT_MAX;
            if (!(mq0 && mc1)) sc[nt][1] = -FLT_MAX;
            if (!(mq1 && mc0)) sc[nt][2] = -FLT_MAX;
            if (!(mq1 && mc1)) sc[nt][3] = -FLT_MAX;
            t0 = fmaxf(t0, fmaxf(sc[nt][0], sc[nt][1]));
            t1 = fmaxf(t1, fmaxf(sc[nt][2], sc[nt][3]));
        }
        t0 = fmaxf(t0, __shfl_xor_sync(0xffffffffu, t0, 1));
        t0 = fmaxf(t0, __shfl_xor_sync(0xffffffffu, t0, 2));
        t1 = fmaxf(t1, __shfl_xor_sync(0xffffffffu, t1, 1));
        t1 = fmaxf(t1, __shfl_xor_sync(0xffffffffu, t1, 2));

        float mn0 = fmaxf(m0, t0), mn1 = fmaxf(m1, t1);
        float al0 = __expf(m0 - mn0), al1 = __expf(m1 - mn1);
        m0 = mn0; m1 = mn1;

        float ps0 = 0.f, ps1 = 0.f;
#pragma unroll
        for (int nt = 0; nt < 8; ++nt) {
            sc[nt][0] = __expf(sc[nt][0] - mn0);
            sc[nt][1] = __expf(sc[nt][1] - mn0);
            sc[nt][2] = __expf(sc[nt][2] - mn1);
            sc[nt][3] = __expf(sc[nt][3] - mn1);
            ps0 += sc[nt][0] + sc[nt][1];
            ps1 += sc[nt][2] + sc[nt][3];
        }
        ps0 += __shfl_xor_sync(0xffffffffu, ps0, 1);
        ps0 += __shfl_xor_sync(0xffffffffu, ps0, 2);
        ps1 += __shfl_xor_sync(0xffffffffu, ps1, 1);
        ps1 += __shfl_xor_sync(0xffffffffu, ps1, 2);
        l0 = l0 * al0 + ps0;
        l1 = l1 * al1 + ps1;

#pragma unroll
        for (int nt = 0; nt < 8; ++nt) {
            O[nt][0] *= al0; O[nt][1] *= al0;
            O[nt][2] *= al1; O[nt][3] *= al1;
        }

        const int srcA = (l & ~3) + (lr >> 1);
        const bool par = (lr & 1) != 0;
#pragma unroll
        for (int kk = 0; kk < 8; ++kk) {
            float x0 = __shfl_sync(0xffffffffu, sc[kk][0], srcA);
            float x1 = __shfl_sync(0xffffffffu, sc[kk][1], srcA);
            float x2 = __shfl_sync(0xffffffffu, sc[kk][2], srcA);
            float x3 = __shfl_sync(0xffffffffu, sc[kk][3], srcA);
            float y0 = __shfl_sync(0xffffffffu, sc[kk][0], srcA + 2);
            float y1 = __shfl_sync(0xffffffffu, sc[kk][1], srcA + 2);
            float y2 = __shfl_sync(0xffffffffu, sc[kk][2], srcA + 2);
            float y3 = __shfl_sync(0xffffffffu, sc[kk][3], srcA + 2);
            unsigned aP[4];
            aP[0] = tf32_of(par ? x1 : x0);
            aP[1] = tf32_of(par ? x3 : x2);
            aP[2] = tf32_of(par ? y1 : y0);
            aP[3] = tf32_of(par ? y3 : y2);
#pragma unroll
            for (int nt = 0; nt < 8; ++nt) {
                unsigned bv[2];
                bv[0] = __float_as_uint(Vs[kk * 8 + lr][nt * 8 + lq]);
                bv[1] = __float_as_uint(Vs[kk * 8 + lr + 4][nt * 8 + lq]);
                mma_tf32(O[nt], aP, bv);
            }
        }
    }

    const float inv0 = 1.f / l0;
    const float inv1 = 1.f / l1;
    float* orow0 = g_ao + ((size_t)b * SEQ + r0) * DIM + h * HD;
    float* orow1 = orow0 + 8 * DIM;
#pragma unroll
    for (int nt = 0; nt < 8; ++nt) {
        int c = nt * 8 + lr * 2;
        *(float2*)&orow0[c] = make_float2(O[nt][0] * inv0, O[nt][1] * inv0);
        *(float2*)&orow1[c] = make_float2(O[nt][2] * inv1, O[nt][3] * inv1);
    }
}

// ---------------------------------------------------------------------------
// Kernel 3: out = g_ao @ w_proj^T + b_proj on tensor cores (tf32 x3).
// M=8192, N=384, K=384.
// ---------------------------------------------------------------------------
__global__ __launch_bounds__(256, 2) void proj_gemm_tc(
    const float* __restrict__ w, const float* __restrict__ bias,
    float* __restrict__ out)
{
    __shared__ __align__(16) float As[2][128][20];
    __shared__ __align__(16) float Bs[2][64][20];

    const int bx = blockIdx.x;          // n-tile, 6
    const int by = blockIdx.y;          // m-tile, 64
    const int tid = threadIdx.x;
    const int wid = tid >> 5;
    const int l   = tid & 31;
    const int lq  = l >> 2;
    const int lr  = l & 3;
    const int wm  = (wid >> 1) * 32;
    const int wn  = (wid & 1) * 32;
    const int m0 = by * 128, n0 = bx * 64;

    const int lrow = tid >> 2;
    const int lkc  = (tid & 3) << 2;

    float C[2][4][4] = {};

    CP16(&As[0][lrow][lkc],      &g_ao[(size_t)(m0 + lrow) * DIM + lkc]);
    CP16(&As[0][lrow + 64][lkc], &g_ao[(size_t)(m0 + lrow + 64) * DIM + lkc]);
    CP16(&Bs[0][lrow][lkc],      &w[(size_t)(n0 + lrow) * DIM + lkc]);
    asm volatile("cp.async.commit_group;" ::: "memory");

    const int NITER = DIM / 16;
    for (int it = 0; it < NITER; ++it) {
        if (it + 1 < NITER) {
            int k0 = (it + 1) * 16;
            int nb = (it + 1) & 1;
            CP16(&As[nb][lrow][lkc],      &g_ao[(size_t)(m0 + lrow) * DIM + k0 + lkc]);
            CP16(&As[nb][lrow + 64][lkc], &g_ao[(size_t)(m0 + lrow + 64) * DIM + k0 + lkc]);
            CP16(&Bs[nb][lrow][lkc],      &w[(size_t)(n0 + lrow) * DIM + k0 + lkc]);
            asm volatile("cp.async.commit_group;" ::: "memory");
            asm volatile("cp.async.wait_group 1;" ::: "memory");
        } else {
            asm volatile("cp.async.wait_group 0;" ::: "memory");
        }
        __syncthreads();
        const int buf = it & 1;

#pragma unroll
        for (int ks = 0; ks < 2; ++ks) {
            const int kb = ks * 8;
            unsigned ah[2][4], al[2][4];
#pragma unroll
            for (int mt = 0; mt < 2; ++mt) {
                float a0 = As[buf][wm + mt * 16 + lq][kb + lr];
                float a1 = As[buf][wm + mt * 16 + lq + 8][kb + lr];
                float a2 = As[buf][wm + mt * 16 + lq][kb + lr + 4];
                float a3 = As[buf][wm + mt * 16 + lq + 8][kb + lr + 4];
                ah[mt][0] = tf32_of(a0); al[mt][0] = tf32_of(a0 - __uint_as_float(ah[mt][0]));
                ah[mt][1] = tf32_of(a1); al[mt][1] = tf32_of(a1 - __uint_as_float(ah[mt][1]));
                ah[mt][2] = tf32_of(a2); al[mt][2] = tf32_of(a2 - __uint_as_float(ah[mt][2]));
                ah[mt][3] = tf32_of(a3); al[mt][3] = tf32_of(a3 - __uint_as_float(ah[mt][3]));
            }
            unsigned bh[4][2], bl[4][2];
#pragma unroll
            for (int nt = 0; nt < 4; ++nt) {
                float b0 = Bs[buf][wn + nt * 8 + lq][kb + lr];
                float b1 = Bs[buf][wn + nt * 8 + lq][kb + lr + 4];
                bh[nt][0] = tf32_of(b0); bl[nt][0] = tf32_of(b0 - __uint_as_float(bh[nt][0]));
                bh[nt][1] = tf32_of(b1); bl[nt][1] = tf32_of(b1 - __uint_as_float(bh[nt][1]));
            }
#pragma unroll
            for (int mt = 0; mt < 2; ++mt)
#pragma unroll
                for (int nt = 0; nt < 4; ++nt) {
                    mma_tf32(C[mt][nt], al[mt], bh[nt]);
                    mma_tf32(C[mt][nt], ah[mt], bl[nt]);
                    mma_tf32(C[mt][nt], ah[mt], bh[nt]);
                }
        }
        __syncthreads();
    }

#pragma unroll
    for (int mt = 0; mt < 2; ++mt) {
        int m = m0 + wm + mt * 16 + lq;
#pragma unroll
        for (int nt = 0; nt < 4; ++nt) {
            int n = n0 + wn + nt * 8 + lr * 2;
            float b0 = bias[n], b1 = bias[n + 1];
            *(float2*)&out[(size_t)m * DIM + n] =
                make_float2(C[mt][nt][0] + b0, C[mt][nt][1] + b1);
            *(float2*)&out[(size_t)(m + 8) * DIM + n] =
                make_float2(C[mt][nt][2] + b0, C[mt][nt][3] + b1);
        }
    }
}

// ---------------------------------------------------------------------------
extern "C" void kernel_launch(void* const* d_in, const int* in_sizes, int n_in,
                              void* d_out, int out_size)
{
    const float* x      = (const float*)d_in[0];
    const int*   mask   = (const int*)d_in[1];     // JAX bool -> int32
    const float* w_qkv  = (const float*)d_in[2];
    const float* w_proj = (const float*)d_in[3];
    const float* b_proj = (const float*)d_in[4];
    float*       out    = (float*)d_out;

    dim3 g1(3 * DIM / 64, (BATCH * SEQ) / 128);  // (18, 64)
    qkv_gemm_tc<<<g1, 256>>>(x, w_qkv);

    dim3 g2(SEQ / 128, BATCH * HEADS);           // (32, 12)
    attn_kernel<<<g2, 256>>>(mask);

    dim3 g3(DIM / 64, (BATCH * SEQ) / 128);      // (6, 64)
    proj_gemm_tc<<<g3, 256>>>(w_proj, b_proj, out);
}